// round 14
// baseline (speedup 1.0000x reference)
#include <cuda_runtime.h>
#include <cuda_bf16.h>
#include <math.h>

// B=4, H=W=704, M=32, P=128, NN=129, R=1, GAIN=2.0
// Only batch b=3 contributes (reference returns losses[-1]).
//
// Single CTA, 128 threads = 4 warps (one per SMSP), work balanced per warp:
//   every thread t: pos item t (4 gathers) + neg item t (4 gathers;
//                   t==127 folds neg item 128)
//   lanes 0..15 of EACH warp: one reg (m, anchor) task
//   (k = wid*16 + lid, m = k>>1, a = k&1) -> 16 reg tasks/warp:
//   equalizes MUFU + LSU pressure across SMSPs.
// All idx loads issue first (hop 1), then all gathers (hop 2), then compute.
// CE via softplus identity (2 MUFU/pair); reg divides via __fdividef.
//
// Design space closed by measurement:
//   1 warp  = 6.88us (MUFU serialized on one SMSP)
//   12 CTAs = 8.93us (cross-CTA reduction tail)
//   8 warps / 256 thr = 7.52us (warm-path issue/barrier overhead)
//   4 warps = {6.62, 7.30, 6.91}us on identical source -> run-to-run noise
//   (~0.3us sigma) exceeds the remaining warm-body budget (~0.4us over the
//   ~6.2us replay floor; two dependent L2 hops are irreducible). Terminal.

#define HH 704
#define WW 704
#define HWSZ (HH * WW)
#define BM 32
#define PP 128
#define NNEG 129
#define GAIN_F 2.0f
#define NTHR 128

__device__ __forceinline__ float softplus(float d) {
    // log(1 + exp(d)) computed stably: max(d,0) + log(1 + exp(-|d|))
    return fmaxf(d, 0.0f) + __logf(1.0f + __expf(-fabsf(d)));
}

__device__ __forceinline__ float smooth_l1(float d) {
    float a = fabsf(d);
    return (a < 1.0f) ? 0.5f * d * d : a - 0.5f;
}

__global__ void __launch_bounds__(NTHR, 1) loss_total_kernel(
    const float* __restrict__ ref_boxes,     // (B,M,7)
    const float* __restrict__ pred_class,    // (B,4,H,W)
    const float* __restrict__ pred_regress,  // (B,14,H,W)
    const float* __restrict__ anchor,        // (2,7,H,W)
    const int*   __restrict__ pos_idx,       // (B,P,2)
    const int*   __restrict__ neg_idx,       // (B,NN,2)
    const int*   __restrict__ reg_idx,       // (B,M,1,2)
    float* __restrict__ out)
{
    const int t   = threadIdx.x;
    const int wid = t >> 5;
    const int lid = t & 31;

    // batch b=3 base offsets
    const float* pc = pred_class   + (size_t)3 * 4  * HWSZ;
    const float* pr = pred_regress + (size_t)3 * 14 * HWSZ;
    const float* rb = ref_boxes    + 3 * BM * 7;
    const int2*  pi = (const int2*)(pos_idx + 3 * PP * 2);
    const int2*  ni = (const int2*)(neg_idx + 3 * NNEG * 2);
    const int2*  ri = (const int2*)(reg_idx + 3 * BM * 2);

    // reg task: 16 per warp on lanes 0..15
    const bool has_reg = (lid < 16);
    const int  k = wid * 16 + lid;          // 0..63 on active lanes
    const int  m = (k >> 1) & (BM - 1);
    const int  a = k & 1;

    // ---- hop 1: all index loads (independent) ----
    int2 ip = pi[t];
    int2 in2 = ni[t];
    int2 ix = ni[(t == 127) ? 128 : 0];     // broadcast addr for t!=127
    int2 ir = ri[has_reg ? m : 0];

    // ref box (small sequential array, independent of idx chain)
    float rv[7];
    #pragma unroll
    for (int c = 0; c < 7; c++) rv[c] = rb[(has_reg ? m : 0) * 7 + c];

    // ---- hop 2: all gathers ----
    int offp = ip.x * WW + ip.y;
    int offn = in2.x * WW + in2.y;
    int offx = ix.x * WW + ix.y;
    int offr = ir.x * WW + ir.y;

    float P0 = pc[0 * HWSZ + offp], P1 = pc[1 * HWSZ + offp];
    float P2 = pc[2 * HWSZ + offp], P3 = pc[3 * HWSZ + offp];
    float N0 = pc[0 * HWSZ + offn], N1 = pc[1 * HWSZ + offn];
    float N2 = pc[2 * HWSZ + offn], N3 = pc[3 * HWSZ + offn];
    float X0 = pc[0 * HWSZ + offx], X1 = pc[1 * HWSZ + offx];
    float X2 = pc[2 * HWSZ + offx], X3 = pc[3 * HWSZ + offx];

    float av[7], pv[7];
    #pragma unroll
    for (int c = 0; c < 7; c++)
        av[c] = anchor[((size_t)(a * 7 + c)) * HWSZ + offr];
    #pragma unroll
    for (int c = 0; c < 7; c++)
        pv[c] = pr[((size_t)(a * 7 + c)) * HWSZ + offr];

    // ---- compute ----
    // positives (label 1): lse(l0,l1)-l1 = softplus(l0-l1)
    float local = (softplus(P0 - P1) + softplus(P2 - P3)) * (1.0f / (float)PP);
    // negatives (label 0): lse(l0,l1)-l0 = softplus(l1-l0)
    local += (softplus(N1 - N0) + softplus(N3 - N2)) * (1.0f / (float)NNEG);
    if (t == 127)
        local += (softplus(X1 - X0) + softplus(X3 - X2)) * (1.0f / (float)NNEG);

    if (has_reg) {
        float inv_diag = rsqrtf(av[3] * av[3] + av[4] * av[4]);
        float o0 = (rv[0] - av[0]) * inv_diag;
        float o1 = (rv[1] - av[1]) * inv_diag;
        float o2 = __fdividef(rv[2] - av[2], av[5]);
        float o3 = __logf(__fdividef(rv[3], av[3]));
        float o4 = __logf(__fdividef(rv[4], av[4]));
        float o5 = __logf(__fdividef(rv[5], av[5]));
        // arctan2(sin(dth), cos(dth)) == wrap dth into (-pi, pi]
        float dth = rv[6] - av[6];
        float o6 = dth - 6.28318530717958647692f *
                         rintf(dth * 0.15915494309189533577f);

        float s = smooth_l1(pv[0] - o0) + smooth_l1(pv[1] - o1)
                + smooth_l1(pv[2] - o2) + smooth_l1(pv[3] - o3)
                + smooth_l1(pv[4] - o4) + smooth_l1(pv[5] - o5)
                + smooth_l1(pv[6] - o6);
        local += GAIN_F * s * (1.0f / 14.0f);
    }

    // ---- reduction: intra-warp shuffle, 4-slot smem, lane0 vec-load finish ----
    #pragma unroll
    for (int s = 16; s > 0; s >>= 1)
        local += __shfl_xor_sync(0xFFFFFFFFu, local, s);

    __shared__ __align__(16) float wsum[4];
    if (lid == 0) wsum[wid] = local;
    __syncthreads();

    if (t == 0) {
        float4 w = *reinterpret_cast<const float4*>(wsum);
        out[0] = (w.x + w.y) + (w.z + w.w);
    }
}

extern "C" void kernel_launch(void* const* d_in, const int* in_sizes, int n_in,
                              void* d_out, int out_size) {
    const float* ref_boxes    = (const float*)d_in[0];
    const float* pred_class   = (const float*)d_in[1];
    const float* pred_regress = (const float*)d_in[2];
    const float* anchor       = (const float*)d_in[3];
    const int*   pos_idx      = (const int*)d_in[4];
    const int*   neg_idx      = (const int*)d_in[5];
    const int*   reg_idx      = (const int*)d_in[6];
    float* out = (float*)d_out;

    loss_total_kernel<<<1, NTHR>>>(ref_boxes, pred_class, pred_regress, anchor,
                                   pos_idx, neg_idx, reg_idx, out);
}

// round 15
// speedup vs baseline: 1.1019x; 1.1019x over previous
#include <cuda_runtime.h>
#include <cuda_bf16.h>
#include <math.h>

// B=4, H=W=704, M=32, P=128, NN=129, R=1, GAIN=2.0
// Only batch b=3 contributes (reference returns losses[-1]).
//
// Single CTA, 128 threads = 4 warps (one per SMSP), work balanced per warp:
//   every thread t: pos item t (4 gathers) + neg item t (4 gathers;
//                   t==127 folds neg item 128)
//   lanes 0..15 of EACH warp: one reg (m, anchor) task
//   (k = wid*16 + lid, m = k>>1, a = k&1) -> 16 reg tasks/warp:
//   equalizes MUFU + LSU pressure across SMSPs.
// All idx loads issue first (hop 1), then all gathers (hop 2), then compute.
// CE via softplus identity (2 MUFU/pair); reg divides via __fdividef.
//
// TERMINAL KERNEL. Design space closed by measurement:
//   1 warp  = 6.88us (MUFU serialized on one SMSP)
//   12 CTAs = 8.93us (cross-CTA reduction tail)
//   8 warps / 256 thr = 7.52us (warm-path issue/barrier overhead)
//   4 warps, identical source, 4 runs = {6.62, 7.30, 6.91, 7.26}us ->
//   run-to-run noise (~0.3us sigma) exceeds the remaining warm-body budget
//   (~0.4us over the ~6.2us replay floor; the two dependent L2 hops
//   idx->gather are irreducible since addresses are data and L1D is
//   flushed per launch).

#define HH 704
#define WW 704
#define HWSZ (HH * WW)
#define BM 32
#define PP 128
#define NNEG 129
#define GAIN_F 2.0f
#define NTHR 128

__device__ __forceinline__ float softplus(float d) {
    // log(1 + exp(d)) computed stably: max(d,0) + log(1 + exp(-|d|))
    return fmaxf(d, 0.0f) + __logf(1.0f + __expf(-fabsf(d)));
}

__device__ __forceinline__ float smooth_l1(float d) {
    float a = fabsf(d);
    return (a < 1.0f) ? 0.5f * d * d : a - 0.5f;
}

__global__ void __launch_bounds__(NTHR, 1) loss_total_kernel(
    const float* __restrict__ ref_boxes,     // (B,M,7)
    const float* __restrict__ pred_class,    // (B,4,H,W)
    const float* __restrict__ pred_regress,  // (B,14,H,W)
    const float* __restrict__ anchor,        // (2,7,H,W)
    const int*   __restrict__ pos_idx,       // (B,P,2)
    const int*   __restrict__ neg_idx,       // (B,NN,2)
    const int*   __restrict__ reg_idx,       // (B,M,1,2)
    float* __restrict__ out)
{
    const int t   = threadIdx.x;
    const int wid = t >> 5;
    const int lid = t & 31;

    // batch b=3 base offsets
    const float* pc = pred_class   + (size_t)3 * 4  * HWSZ;
    const float* pr = pred_regress + (size_t)3 * 14 * HWSZ;
    const float* rb = ref_boxes    + 3 * BM * 7;
    const int2*  pi = (const int2*)(pos_idx + 3 * PP * 2);
    const int2*  ni = (const int2*)(neg_idx + 3 * NNEG * 2);
    const int2*  ri = (const int2*)(reg_idx + 3 * BM * 2);

    // reg task: 16 per warp on lanes 0..15
    const bool has_reg = (lid < 16);
    const int  k = wid * 16 + lid;          // 0..63 on active lanes
    const int  m = (k >> 1) & (BM - 1);
    const int  a = k & 1;

    // ---- hop 1: all index loads (independent) ----
    int2 ip = pi[t];
    int2 in2 = ni[t];
    int2 ix = ni[(t == 127) ? 128 : 0];     // broadcast addr for t!=127
    int2 ir = ri[has_reg ? m : 0];

    // ref box (small sequential array, independent of idx chain)
    float rv[7];
    #pragma unroll
    for (int c = 0; c < 7; c++) rv[c] = rb[(has_reg ? m : 0) * 7 + c];

    // ---- hop 2: all gathers ----
    int offp = ip.x * WW + ip.y;
    int offn = in2.x * WW + in2.y;
    int offx = ix.x * WW + ix.y;
    int offr = ir.x * WW + ir.y;

    float P0 = pc[0 * HWSZ + offp], P1 = pc[1 * HWSZ + offp];
    float P2 = pc[2 * HWSZ + offp], P3 = pc[3 * HWSZ + offp];
    float N0 = pc[0 * HWSZ + offn], N1 = pc[1 * HWSZ + offn];
    float N2 = pc[2 * HWSZ + offn], N3 = pc[3 * HWSZ + offn];
    float X0 = pc[0 * HWSZ + offx], X1 = pc[1 * HWSZ + offx];
    float X2 = pc[2 * HWSZ + offx], X3 = pc[3 * HWSZ + offx];

    float av[7], pv[7];
    #pragma unroll
    for (int c = 0; c < 7; c++)
        av[c] = anchor[((size_t)(a * 7 + c)) * HWSZ + offr];
    #pragma unroll
    for (int c = 0; c < 7; c++)
        pv[c] = pr[((size_t)(a * 7 + c)) * HWSZ + offr];

    // ---- compute ----
    // positives (label 1): lse(l0,l1)-l1 = softplus(l0-l1)
    float local = (softplus(P0 - P1) + softplus(P2 - P3)) * (1.0f / (float)PP);
    // negatives (label 0): lse(l0,l1)-l0 = softplus(l1-l0)
    local += (softplus(N1 - N0) + softplus(N3 - N2)) * (1.0f / (float)NNEG);
    if (t == 127)
        local += (softplus(X1 - X0) + softplus(X3 - X2)) * (1.0f / (float)NNEG);

    if (has_reg) {
        float inv_diag = rsqrtf(av[3] * av[3] + av[4] * av[4]);
        float o0 = (rv[0] - av[0]) * inv_diag;
        float o1 = (rv[1] - av[1]) * inv_diag;
        float o2 = __fdividef(rv[2] - av[2], av[5]);
        float o3 = __logf(__fdividef(rv[3], av[3]));
        float o4 = __logf(__fdividef(rv[4], av[4]));
        float o5 = __logf(__fdividef(rv[5], av[5]));
        // arctan2(sin(dth), cos(dth)) == wrap dth into (-pi, pi]
        float dth = rv[6] - av[6];
        float o6 = dth - 6.28318530717958647692f *
                         rintf(dth * 0.15915494309189533577f);

        float s = smooth_l1(pv[0] - o0) + smooth_l1(pv[1] - o1)
                + smooth_l1(pv[2] - o2) + smooth_l1(pv[3] - o3)
                + smooth_l1(pv[4] - o4) + smooth_l1(pv[5] - o5)
                + smooth_l1(pv[6] - o6);
        local += GAIN_F * s * (1.0f / 14.0f);
    }

    // ---- reduction: intra-warp shuffle, 4-slot smem, lane0 vec-load finish ----
    #pragma unroll
    for (int s = 16; s > 0; s >>= 1)
        local += __shfl_xor_sync(0xFFFFFFFFu, local, s);

    __shared__ __align__(16) float wsum[4];
    if (lid == 0) wsum[wid] = local;
    __syncthreads();

    if (t == 0) {
        float4 w = *reinterpret_cast<const float4*>(wsum);
        out[0] = (w.x + w.y) + (w.z + w.w);
    }
}

extern "C" void kernel_launch(void* const* d_in, const int* in_sizes, int n_in,
                              void* d_out, int out_size) {
    const float* ref_boxes    = (const float*)d_in[0];
    const float* pred_class   = (const float*)d_in[1];
    const float* pred_regress = (const float*)d_in[2];
    const float* anchor       = (const float*)d_in[3];
    const int*   pos_idx      = (const int*)d_in[4];
    const int*   neg_idx      = (const int*)d_in[5];
    const int*   reg_idx      = (const int*)d_in[6];
    float* out = (float*)d_out;

    loss_total_kernel<<<1, NTHR>>>(ref_boxes, pred_class, pred_regress, anchor,
                                   pos_idx, neg_idx, reg_idx, out);
}